// round 2
// baseline (speedup 1.0000x reference)
#include <cuda_runtime.h>
#include <cstdint>

#define N_NODES 100000
#define N_EDGES 1600000
#define HID 64

// Scratch for x@W per layer: 100000 x 64 fp32 = 25.6 MB (device global: allowed)
__device__ float g_xw[(size_t)N_NODES * HID];
// 1 if edge_index is int64, 0 if int32 (JAX default x64-disabled silently gives int32)
__device__ int g_idx_is64;

// ---------------------------------------------------------------------------
// Detect edge-index dtype on-device (deterministic, capture-safe).
// If int64: high word of every entry is 0 and low word < N_NODES.
// If int32: odd words are random node ids -> essentially never all zero.
// ---------------------------------------------------------------------------
__global__ void detect_idx(const int* __restrict__ ei_raw) {
    if (threadIdx.x == 0 && blockIdx.x == 0) {
        int is64 = 1;
        for (int i = 0; i < 256; i++) {
            int lo = ei_raw[2 * i];
            int hi = ei_raw[2 * i + 1];
            if (hi != 0 || (unsigned)lo >= (unsigned)N_NODES) { is64 = 0; break; }
        }
        g_idx_is64 = is64;
    }
}

// ---------------------------------------------------------------------------
// GEMM: Y[n, 0..63] = X[n, 0..K-1] @ W[K, 64]
// Block tile: 64 rows x 64 cols, 256 threads (16x16), each thread 4x4 outputs.
// ---------------------------------------------------------------------------
template <int K>
__global__ __launch_bounds__(256) void gemm64(const float* __restrict__ X,
                                              const float* __restrict__ W,
                                              float* __restrict__ Y,
                                              int nrows) {
    __shared__ float sW[K * 64];
    __shared__ float sX[64 * 64];

    const int tx = threadIdx.x;          // 0..15  (col group)
    const int ty = threadIdx.y;          // 0..15  (row group)
    const int tid = ty * 16 + tx;
    const int row0 = blockIdx.x * 64;

    for (int i = tid; i < K * 64; i += 256) sW[i] = W[i];

    float acc[4][4] = {};

    for (int kc = 0; kc < K; kc += 64) {
        __syncthreads();  // iter 0: sW visible; later: previous compute done
        for (int i = tid; i < 64 * 64; i += 256) {
            int r = i >> 6, k = i & 63;
            int row = row0 + r;
            sX[i] = (row < nrows) ? X[(size_t)row * K + kc + k] : 0.0f;
        }
        __syncthreads();

        #pragma unroll 16
        for (int k = 0; k < 64; k++) {
            float xv[4], wv[4];
            #pragma unroll
            for (int r = 0; r < 4; r++) xv[r] = sX[(ty * 4 + r) * 64 + k];
            #pragma unroll
            for (int c = 0; c < 4; c++) wv[c] = sW[(kc + k) * 64 + tx * 4 + c];
            #pragma unroll
            for (int r = 0; r < 4; r++)
                #pragma unroll
                for (int c = 0; c < 4; c++)
                    acc[r][c] = fmaf(xv[r], wv[c], acc[r][c]);
        }
    }

    #pragma unroll
    for (int r = 0; r < 4; r++) {
        int row = row0 + ty * 4 + r;
        if (row < nrows) {
            float4 v = make_float4(acc[r][0], acc[r][1], acc[r][2], acc[r][3]);
            *reinterpret_cast<float4*>(Y + (size_t)row * 64 + tx * 4) = v;
        }
    }
}

// ---------------------------------------------------------------------------
// out[n, c] = b[c]  (broadcast bias init; scatter accumulates on top)
// ---------------------------------------------------------------------------
__global__ __launch_bounds__(256) void bias_init(float* __restrict__ out,
                                                 const float* __restrict__ b) {
    int i = blockIdx.x * 256 + threadIdx.x;
    if (i < N_NODES * 16) {
        float4 bv = reinterpret_cast<const float4*>(b)[i & 15];
        reinterpret_cast<float4*>(out)[i] = bv;
    }
}

// ---------------------------------------------------------------------------
// Scatter-add: out[dst[e], :] += xw[src[e], :]
// 16 threads per edge, one float4 per thread, vectorized L2 reduction.
// Index dtype (int32 vs int64) selected by g_idx_is64 (uniform branch).
// ---------------------------------------------------------------------------
__global__ __launch_bounds__(256) void scatter64(const float* __restrict__ xw,
                                                 const int* __restrict__ ei32,
                                                 float* __restrict__ out) {
    int tid = blockIdx.x * 256 + threadIdx.x;      // 25.6M total, fits in int
    if (tid >= N_EDGES * 16) return;
    int e = tid >> 4;
    int q = tid & 15;

    int src, dst;
    if (g_idx_is64) {                 // int64: low word at 2*idx (little-endian)
        src = __ldg(&ei32[2 * (size_t)e]);
        dst = __ldg(&ei32[2 * ((size_t)N_EDGES + e)]);
    } else {                          // int32
        src = __ldg(&ei32[e]);
        dst = __ldg(&ei32[N_EDGES + e]);
    }

    float4 v = *reinterpret_cast<const float4*>(xw + (size_t)src * 64 + q * 4);
    float* p = out + (size_t)dst * 64 + q * 4;

    asm volatile("red.relaxed.gpu.global.add.v4.f32 [%0], {%1, %2, %3, %4};"
                 :: "l"(p), "f"(v.x), "f"(v.y), "f"(v.z), "f"(v.w)
                 : "memory");
}

// ---------------------------------------------------------------------------
extern "C" void kernel_launch(void* const* d_in, const int* in_sizes, int n_in,
                              void* d_out, int out_size) {
    const float* x  = (const float*)d_in[0];
    const int*   ei = (const int*)d_in[1];     // raw words; dtype auto-detected
    const float* W1 = (const float*)d_in[2];
    const float* b1 = (const float*)d_in[3];
    const float* W2 = (const float*)d_in[4];
    const float* b2 = (const float*)d_in[5];
    const float* W3 = (const float*)d_in[6];
    const float* b3 = (const float*)d_in[7];

    float* h1 = (float*)d_out;
    float* h2 = h1 + (size_t)N_NODES * HID;
    float* h3 = h2 + (size_t)N_NODES * HID;

    float* xw;
    cudaGetSymbolAddress((void**)&xw, g_xw);

    const dim3 gblk(16, 16);
    const int  ggrid = (N_NODES + 63) / 64;
    const int  bgrid = (N_NODES * 16 + 255) / 256;
    const int  sgrid = (N_EDGES * 16) / 256;

    detect_idx<<<1, 32>>>(ei);

    // Layer 1: x[N,128] @ W1 -> scatter -> h1
    gemm64<128><<<ggrid, gblk>>>(x, W1, xw, N_NODES);
    bias_init<<<bgrid, 256>>>(h1, b1);
    scatter64<<<sgrid, 256>>>(xw, ei, h1);

    // Layer 2: h1 @ W2 -> scatter -> h2
    gemm64<64><<<ggrid, gblk>>>(h1, W2, xw, N_NODES);
    bias_init<<<bgrid, 256>>>(h2, b2);
    scatter64<<<sgrid, 256>>>(xw, ei, h2);

    // Layer 3: h2 @ W3 -> scatter -> h3
    gemm64<64><<<ggrid, gblk>>>(h2, W3, xw, N_NODES);
    bias_init<<<bgrid, 256>>>(h3, b3);
    scatter64<<<sgrid, 256>>>(xw, ei, h3);
}

// round 3
// speedup vs baseline: 1.2919x; 1.2919x over previous
#include <cuda_runtime.h>
#include <cstdint>

#define N_NODES 100000
#define N_EDGES 1600000
#define HID 64

// ---- device-global scratch (no allocations allowed) ----
__device__ float g_xw[(size_t)N_NODES * HID];   // x @ W per layer (25.6 MB)
__device__ int   g_deg[N_NODES];                // in-degree counts / cursors
__device__ int   g_off[N_NODES + 1];            // CSR row offsets (by dst)
__device__ int   g_col[N_EDGES];                // CSR column = src node per slot
__device__ int   g_idx_is64;                    // edge_index dtype flag

// ---------------------------------------------------------------------------
// Detect edge-index dtype on-device (deterministic, capture-safe).
// int64 => high word of every entry 0 and low word < N_NODES.
// ---------------------------------------------------------------------------
__global__ void detect_idx(const int* __restrict__ ei_raw) {
    if (threadIdx.x == 0 && blockIdx.x == 0) {
        int is64 = 1;
        for (int i = 0; i < 256; i++) {
            int lo = ei_raw[2 * i];
            int hi = ei_raw[2 * i + 1];
            if (hi != 0 || (unsigned)lo >= (unsigned)N_NODES) { is64 = 0; break; }
        }
        g_idx_is64 = is64;
    }
}

__device__ __forceinline__ int load_idx(const int* __restrict__ ei, size_t pos) {
    // pos in [0, 2*N_EDGES): logical element index of the edge_index array
    return g_idx_is64 ? __ldg(&ei[2 * pos]) : __ldg(&ei[pos]);
}

// ---------------------------------------------------------------------------
// CSR build
// ---------------------------------------------------------------------------
__global__ __launch_bounds__(256) void zero_deg() {
    int i = blockIdx.x * 256 + threadIdx.x;
    if (i < N_NODES) g_deg[i] = 0;
}

__global__ __launch_bounds__(256) void count_deg(const int* __restrict__ ei) {
    int e = blockIdx.x * 256 + threadIdx.x;
    if (e < N_EDGES) {
        int dst = load_idx(ei, (size_t)N_EDGES + e);
        atomicAdd(&g_deg[dst], 1);
    }
}

// Single-block exclusive scan of g_deg -> g_off, and reset g_deg to 0 (cursors).
__global__ __launch_bounds__(1024) void scan_deg() {
    __shared__ int warpsums[32];
    const int tid = threadIdx.x, lane = tid & 31, wid = tid >> 5;
    int carry = 0;
    for (int base = 0; base < N_NODES; base += 1024) {
        int i = base + tid;
        int v = (i < N_NODES) ? g_deg[i] : 0;
        // warp inclusive scan
        int s = v;
        #pragma unroll
        for (int d = 1; d < 32; d <<= 1) {
            int t = __shfl_up_sync(0xffffffffu, s, d);
            if (lane >= d) s += t;
        }
        if (lane == 31) warpsums[wid] = s;
        __syncthreads();
        if (wid == 0) {
            int ws = warpsums[lane];
            #pragma unroll
            for (int d = 1; d < 32; d <<= 1) {
                int t = __shfl_up_sync(0xffffffffu, ws, d);
                if (lane >= d) ws += t;
            }
            warpsums[lane] = ws;
        }
        __syncthreads();
        int warpoff = (wid == 0) ? 0 : warpsums[wid - 1];
        if (i < N_NODES) {
            g_off[i] = carry + warpoff + s - v;   // exclusive prefix
            g_deg[i] = 0;                          // reset as fill cursor
        }
        carry += warpsums[31];
        __syncthreads();
    }
    if (tid == 0) g_off[N_NODES] = carry;
}

__global__ __launch_bounds__(256) void fill_csr(const int* __restrict__ ei) {
    int e = blockIdx.x * 256 + threadIdx.x;
    if (e < N_EDGES) {
        int src = load_idx(ei, (size_t)e);
        int dst = load_idx(ei, (size_t)N_EDGES + e);
        int slot = g_off[dst] + atomicAdd(&g_deg[dst], 1);
        g_col[slot] = src;
    }
}

// ---------------------------------------------------------------------------
// GEMM: Y[n, 0..63] = X[n, 0..K-1] @ W[K, 64]
// 64x64 tile, 256 threads (16x16), 4x4 outputs per thread.
// ---------------------------------------------------------------------------
template <int K>
__global__ __launch_bounds__(256) void gemm64(const float* __restrict__ X,
                                              const float* __restrict__ W,
                                              float* __restrict__ Y,
                                              int nrows) {
    __shared__ float sW[K * 64];
    __shared__ float sX[64 * 64];

    const int tx = threadIdx.x;
    const int ty = threadIdx.y;
    const int tid = ty * 16 + tx;
    const int row0 = blockIdx.x * 64;

    for (int i = tid; i < K * 64; i += 256) sW[i] = W[i];

    float acc[4][4] = {};

    for (int kc = 0; kc < K; kc += 64) {
        __syncthreads();
        for (int i = tid; i < 64 * 64; i += 256) {
            int r = i >> 6, k = i & 63;
            int row = row0 + r;
            sX[i] = (row < nrows) ? X[(size_t)row * K + kc + k] : 0.0f;
        }
        __syncthreads();

        #pragma unroll 16
        for (int k = 0; k < 64; k++) {
            float xv[4], wv[4];
            #pragma unroll
            for (int r = 0; r < 4; r++) xv[r] = sX[(ty * 4 + r) * 64 + k];
            #pragma unroll
            for (int c = 0; c < 4; c++) wv[c] = sW[(kc + k) * 64 + tx * 4 + c];
            #pragma unroll
            for (int r = 0; r < 4; r++)
                #pragma unroll
                for (int c = 0; c < 4; c++)
                    acc[r][c] = fmaf(xv[r], wv[c], acc[r][c]);
        }
    }

    #pragma unroll
    for (int r = 0; r < 4; r++) {
        int row = row0 + ty * 4 + r;
        if (row < nrows) {
            float4 v = make_float4(acc[r][0], acc[r][1], acc[r][2], acc[r][3]);
            *reinterpret_cast<float4*>(Y + (size_t)row * 64 + tx * 4) = v;
        }
    }
}

// ---------------------------------------------------------------------------
// CSR gather-aggregate: out[n,:] = sum_{e in in(n)} xw[col[e],:] + b
// One warp per node. Half-warps (16 lanes) process alternating edges;
// each lane owns one float4 feature chunk. No atomics.
// ---------------------------------------------------------------------------
__global__ __launch_bounds__(256) void gather64(const float* __restrict__ xw,
                                                float* __restrict__ out,
                                                const float* __restrict__ b) {
    int warp_id = (blockIdx.x * 256 + threadIdx.x) >> 5;
    if (warp_id >= N_NODES) return;
    const int lane = threadIdx.x & 31;
    const int half = lane >> 4;            // 0 or 1
    const int q    = lane & 15;            // feature chunk (float4 index)

    const int beg = __ldg(&g_off[warp_id]);
    const int end = __ldg(&g_off[warp_id + 1]);

    float4 acc = make_float4(0.f, 0.f, 0.f, 0.f);
    for (int i = beg + half; i < end; i += 2) {
        int src = __ldg(&g_col[i]);
        float4 v = *reinterpret_cast<const float4*>(xw + (size_t)src * 64 + q * 4);
        acc.x += v.x; acc.y += v.y; acc.z += v.z; acc.w += v.w;
    }
    // combine the two halves
    acc.x += __shfl_xor_sync(0xffffffffu, acc.x, 16);
    acc.y += __shfl_xor_sync(0xffffffffu, acc.y, 16);
    acc.z += __shfl_xor_sync(0xffffffffu, acc.z, 16);
    acc.w += __shfl_xor_sync(0xffffffffu, acc.w, 16);

    if (half == 0) {
        float4 bv = reinterpret_cast<const float4*>(b)[q];
        acc.x += bv.x; acc.y += bv.y; acc.z += bv.z; acc.w += bv.w;
        *reinterpret_cast<float4*>(out + (size_t)warp_id * 64 + q * 4) = acc;
    }
}

// ---------------------------------------------------------------------------
extern "C" void kernel_launch(void* const* d_in, const int* in_sizes, int n_in,
                              void* d_out, int out_size) {
    const float* x  = (const float*)d_in[0];
    const int*   ei = (const int*)d_in[1];     // raw words; dtype auto-detected
    const float* W1 = (const float*)d_in[2];
    const float* b1 = (const float*)d_in[3];
    const float* W2 = (const float*)d_in[4];
    const float* b2 = (const float*)d_in[5];
    const float* W3 = (const float*)d_in[6];
    const float* b3 = (const float*)d_in[7];

    float* h1 = (float*)d_out;
    float* h2 = h1 + (size_t)N_NODES * HID;
    float* h3 = h2 + (size_t)N_NODES * HID;

    float* xw;
    cudaGetSymbolAddress((void**)&xw, g_xw);

    const dim3 gblk(16, 16);
    const int  ggrid = (N_NODES + 63) / 64;
    const int  egrid = (N_EDGES + 255) / 256;
    const int  ngrid = (N_NODES + 255) / 256;
    const int  agrid = (N_NODES * 32 + 255) / 256;   // warp per node

    // --- CSR build (once per call, reused by all 3 layers) ---
    detect_idx<<<1, 32>>>(ei);
    zero_deg<<<ngrid, 256>>>();
    count_deg<<<egrid, 256>>>(ei);
    scan_deg<<<1, 1024>>>();
    fill_csr<<<egrid, 256>>>(ei);

    // --- Layer 1 ---
    gemm64<128><<<ggrid, gblk>>>(x, W1, xw, N_NODES);
    gather64<<<agrid, 256>>>(xw, h1, b1);
    // --- Layer 2 ---
    gemm64<64><<<ggrid, gblk>>>(h1, W2, xw, N_NODES);
    gather64<<<agrid, 256>>>(xw, h2, b2);
    // --- Layer 3 ---
    gemm64<64><<<ggrid, gblk>>>(h2, W3, xw, N_NODES);
    gather64<<<agrid, 256>>>(xw, h3, b3);
}

// round 4
// speedup vs baseline: 1.5954x; 1.2349x over previous
#include <cuda_runtime.h>
#include <cstdint>

#define N_NODES 100000
#define N_EDGES 1600000
#define HID 64

#define SCAN_BLK 1024
#define N_SCAN_BLOCKS ((N_NODES + SCAN_BLK - 1) / SCAN_BLK)   // 98

// ---- device-global scratch (no allocations allowed) ----
__device__ float g_xw[(size_t)N_NODES * HID];   // x @ W per layer (25.6 MB)
__device__ int   g_deg[N_NODES];                // in-degree counts / cursors
__device__ int   g_off[N_NODES + 1];            // CSR row offsets (by dst)
__device__ int   g_col[N_EDGES];                // CSR column = src node per slot
__device__ int   g_part[N_SCAN_BLOCKS];         // per-block partial sums
__device__ int   g_idx_is64;                    // edge_index dtype flag

// ---------------------------------------------------------------------------
// Detect edge-index dtype on-device (deterministic, capture-safe).
// ---------------------------------------------------------------------------
__global__ void detect_idx(const int* __restrict__ ei_raw) {
    if (threadIdx.x == 0 && blockIdx.x == 0) {
        int is64 = 1;
        for (int i = 0; i < 256; i++) {
            int lo = ei_raw[2 * i];
            int hi = ei_raw[2 * i + 1];
            if (hi != 0 || (unsigned)lo >= (unsigned)N_NODES) { is64 = 0; break; }
        }
        g_idx_is64 = is64;
    }
}

__device__ __forceinline__ int load_idx(const int* __restrict__ ei, size_t pos) {
    return g_idx_is64 ? __ldg(&ei[2 * pos]) : __ldg(&ei[pos]);
}

// ---------------------------------------------------------------------------
// CSR build
// ---------------------------------------------------------------------------
__global__ __launch_bounds__(256) void zero_deg() {
    int i = blockIdx.x * 256 + threadIdx.x;
    if (i < N_NODES) g_deg[i] = 0;
}

__global__ __launch_bounds__(256) void count_deg(const int* __restrict__ ei) {
    int e = blockIdx.x * 256 + threadIdx.x;
    if (e < N_EDGES) {
        int dst = load_idx(ei, (size_t)N_EDGES + e);
        atomicAdd(&g_deg[dst], 1);
    }
}

// --- multi-block exclusive scan of g_deg -> g_off ---
// A) per-block exclusive scan; block total -> g_part[b]
__global__ __launch_bounds__(SCAN_BLK) void scan_blocks() {
    __shared__ int warpsums[32];
    const int tid = threadIdx.x, lane = tid & 31, wid = tid >> 5;
    const int i = blockIdx.x * SCAN_BLK + tid;

    int v = (i < N_NODES) ? g_deg[i] : 0;
    int s = v;
    #pragma unroll
    for (int d = 1; d < 32; d <<= 1) {
        int t = __shfl_up_sync(0xffffffffu, s, d);
        if (lane >= d) s += t;
    }
    if (lane == 31) warpsums[wid] = s;
    __syncthreads();
    if (wid == 0) {
        int ws = warpsums[lane];
        #pragma unroll
        for (int d = 1; d < 32; d <<= 1) {
            int t = __shfl_up_sync(0xffffffffu, ws, d);
            if (lane >= d) ws += t;
        }
        warpsums[lane] = ws;
    }
    __syncthreads();
    int warpoff = (wid == 0) ? 0 : warpsums[wid - 1];
    if (i < N_NODES) g_off[i] = warpoff + s - v;     // block-local exclusive
    if (tid == SCAN_BLK - 1) g_part[blockIdx.x] = warpsums[31];
}

// B) scan the 98 partials in one tiny block (exclusive); store total at end
__global__ __launch_bounds__(128) void scan_partials() {
    __shared__ int warpsums[4];
    const int tid = threadIdx.x, lane = tid & 31, wid = tid >> 5;
    int v = (tid < N_SCAN_BLOCKS) ? g_part[tid] : 0;
    int s = v;
    #pragma unroll
    for (int d = 1; d < 32; d <<= 1) {
        int t = __shfl_up_sync(0xffffffffu, s, d);
        if (lane >= d) s += t;
    }
    if (lane == 31) warpsums[wid] = s;
    __syncthreads();
    int woff = 0;
    for (int w = 0; w < wid; w++) woff += warpsums[w];
    if (tid < N_SCAN_BLOCKS) g_part[tid] = woff + s - v;  // exclusive
    if (tid == 127) g_off[N_NODES] = woff + s;            // total = inclusive of last
}

// C) add block offsets; reset g_deg as fill cursor
__global__ __launch_bounds__(SCAN_BLK) void scan_finish() {
    int i = blockIdx.x * SCAN_BLK + threadIdx.x;
    if (i < N_NODES) {
        g_off[i] += g_part[blockIdx.x];
        g_deg[i] = 0;
    }
}

__global__ __launch_bounds__(256) void fill_csr(const int* __restrict__ ei) {
    int e = blockIdx.x * 256 + threadIdx.x;
    if (e < N_EDGES) {
        int src = load_idx(ei, (size_t)e);
        int dst = load_idx(ei, (size_t)N_EDGES + e);
        int slot = g_off[dst] + atomicAdd(&g_deg[dst], 1);
        g_col[slot] = src;
    }
}

// ---------------------------------------------------------------------------
// GEMM: Y[n, 0..63] = X[n, 0..K-1] @ W[K, 64]
// 64x64 tile, 256 threads (16x16), 4x4 outputs per thread.
// ---------------------------------------------------------------------------
template <int K>
__global__ __launch_bounds__(256) void gemm64(const float* __restrict__ X,
                                              const float* __restrict__ W,
                                              float* __restrict__ Y,
                                              int nrows) {
    __shared__ float sW[K * 64];
    __shared__ float sX[64 * 64];

    const int tx = threadIdx.x;
    const int ty = threadIdx.y;
    const int tid = ty * 16 + tx;
    const int row0 = blockIdx.x * 64;

    for (int i = tid; i < K * 64; i += 256) sW[i] = W[i];

    float acc[4][4] = {};

    for (int kc = 0; kc < K; kc += 64) {
        __syncthreads();
        for (int i = tid; i < 64 * 64; i += 256) {
            int r = i >> 6, k = i & 63;
            int row = row0 + r;
            sX[i] = (row < nrows) ? X[(size_t)row * K + kc + k] : 0.0f;
        }
        __syncthreads();

        #pragma unroll 16
        for (int k = 0; k < 64; k++) {
            float xv[4], wv[4];
            #pragma unroll
            for (int r = 0; r < 4; r++) xv[r] = sX[(ty * 4 + r) * 64 + k];
            #pragma unroll
            for (int c = 0; c < 4; c++) wv[c] = sW[(kc + k) * 64 + tx * 4 + c];
            #pragma unroll
            for (int r = 0; r < 4; r++)
                #pragma unroll
                for (int c = 0; c < 4; c++)
                    acc[r][c] = fmaf(xv[r], wv[c], acc[r][c]);
        }
    }

    #pragma unroll
    for (int r = 0; r < 4; r++) {
        int row = row0 + ty * 4 + r;
        if (row < nrows) {
            float4 v = make_float4(acc[r][0], acc[r][1], acc[r][2], acc[r][3]);
            *reinterpret_cast<float4*>(Y + (size_t)row * 64 + tx * 4) = v;
        }
    }
}

// ---------------------------------------------------------------------------
// CSR gather-aggregate: out[n,:] = sum_{e in in(n)} xw[col[e],:] + b
// One warp per node; half-warps process alternating edges; lane owns a float4.
// ---------------------------------------------------------------------------
__global__ __launch_bounds__(256) void gather64(const float* __restrict__ xw,
                                                float* __restrict__ out,
                                                const float* __restrict__ b) {
    int warp_id = (blockIdx.x * 256 + threadIdx.x) >> 5;
    if (warp_id >= N_NODES) return;
    const int lane = threadIdx.x & 31;
    const int half = lane >> 4;
    const int q    = lane & 15;

    const int beg = __ldg(&g_off[warp_id]);
    const int end = __ldg(&g_off[warp_id + 1]);

    float4 acc = make_float4(0.f, 0.f, 0.f, 0.f);
    for (int i = beg + half; i < end; i += 2) {
        int src = __ldg(&g_col[i]);
        float4 v = *reinterpret_cast<const float4*>(xw + (size_t)src * 64 + q * 4);
        acc.x += v.x; acc.y += v.y; acc.z += v.z; acc.w += v.w;
    }
    acc.x += __shfl_xor_sync(0xffffffffu, acc.x, 16);
    acc.y += __shfl_xor_sync(0xffffffffu, acc.y, 16);
    acc.z += __shfl_xor_sync(0xffffffffu, acc.z, 16);
    acc.w += __shfl_xor_sync(0xffffffffu, acc.w, 16);

    if (half == 0) {
        float4 bv = reinterpret_cast<const float4*>(b)[q];
        acc.x += bv.x; acc.y += bv.y; acc.z += bv.z; acc.w += bv.w;
        *reinterpret_cast<float4*>(out + (size_t)warp_id * 64 + q * 4) = acc;
    }
}

// ---------------------------------------------------------------------------
extern "C" void kernel_launch(void* const* d_in, const int* in_sizes, int n_in,
                              void* d_out, int out_size) {
    const float* x  = (const float*)d_in[0];
    const int*   ei = (const int*)d_in[1];
    const float* W1 = (const float*)d_in[2];
    const float* b1 = (const float*)d_in[3];
    const float* W2 = (const float*)d_in[4];
    const float* b2 = (const float*)d_in[5];
    const float* W3 = (const float*)d_in[6];
    const float* b3 = (const float*)d_in[7];

    float* h1 = (float*)d_out;
    float* h2 = h1 + (size_t)N_NODES * HID;
    float* h3 = h2 + (size_t)N_NODES * HID;

    float* xw;
    cudaGetSymbolAddress((void**)&xw, g_xw);

    const dim3 gblk(16, 16);
    const int  ggrid = (N_NODES + 63) / 64;
    const int  egrid = (N_EDGES + 255) / 256;
    const int  ngrid = (N_NODES + 255) / 256;
    const int  agrid = (N_NODES * 32 + 255) / 256;

    // --- CSR build (multi-block scan) ---
    detect_idx<<<1, 32>>>(ei);
    zero_deg<<<ngrid, 256>>>();
    count_deg<<<egrid, 256>>>(ei);
    scan_blocks<<<N_SCAN_BLOCKS, SCAN_BLK>>>();
    scan_partials<<<1, 128>>>();
    scan_finish<<<N_SCAN_BLOCKS, SCAN_BLK>>>();
    fill_csr<<<egrid, 256>>>(ei);

    // --- Layer 1 ---
    gemm64<128><<<ggrid, gblk>>>(x, W1, xw, N_NODES);
    gather64<<<agrid, 256>>>(xw, h1, b1);
    // --- Layer 2 ---
    gemm64<64><<<ggrid, gblk>>>(h1, W2, xw, N_NODES);
    gather64<<<agrid, 256>>>(xw, h2, b2);
    // --- Layer 3 ---
    gemm64<64><<<ggrid, gblk>>>(h2, W3, xw, N_NODES);
    gather64<<<agrid, 256>>>(xw, h3, b3);
}